// round 12
// baseline (speedup 1.0000x reference)
#include <cuda_runtime.h>
#include <cuda_fp16.h>
#include <stdint.h>

#define N_NODES 50000
#define N_EDGES 1000000
#define F_IN  64
#define F_HID 64
#define F_OUT 32
#define ELL_PAD 64          // P(deg > 64) ~ 1e-15 for Poisson(20); clamped anyway

// ---------------- scratch (device globals: allocation-free rule) ----------------
// g_cnt starts zero (module load). k_dinv consumes it (copy to g_cnts) and
// re-zeroes it, one thread per index -> no cross-block races, launch-invariant.
__device__ __align__(16) __half g_hs1h[N_NODES * F_HID];  // fp16 X@W1 (unscaled)
__device__ __align__(16) float  g_x2  [N_NODES * F_HID];  // relu(agg1 + b1)
__device__ __align__(16) __half g_hs2h[N_NODES * F_OUT];  // fp16 x2@W2 (unscaled)
__device__ float g_dinv[N_NODES];       // rsqrt(deg), deg = cnt+1
__device__ int g_cnt [N_NODES];         // live counter (zeroed by k_dinv)
__device__ int g_cnts[N_NODES];         // stable per-launch copy for the aggs
__device__ int g_ell[N_NODES * ELL_PAD];  // 12.8MB ELL adjacency (src per slot)

// ---------------- single-pass ELL build: 2 edges/thread ----------------
__global__ void k_permute_ell(const int* __restrict__ ei) {
    int i = blockIdx.x * blockDim.x + threadIdx.x;   // pair index
    if (2 * i >= N_EDGES) return;
    int2 sv = ((const int2*)ei)[i];                  // src half
    int2 dv = ((const int2*)(ei + N_EDGES))[i];      // dst half
    int p0 = atomicAdd(&g_cnt[dv.x], 1);
    g_ell[dv.x * ELL_PAD + (p0 < ELL_PAD ? p0 : ELL_PAD - 1)] = sv.x;
    int p1 = atomicAdd(&g_cnt[dv.y], 1);
    g_ell[dv.y * ELL_PAD + (p1 < ELL_PAD ? p1 : ELL_PAD - 1)] = sv.y;
}

// ---------------- dinv + count snapshot + counter reset ----------------
// Thread i owns index i: read, copy, zero. No ordering hazards.
__global__ void k_dinv() {
    int i = blockIdx.x * blockDim.x + threadIdx.x;
    if (i < N_NODES) {
        int c = g_cnt[i];
        g_cnts[i] = c;
        g_cnt[i]  = 0;                   // ready for next launch
        g_dinv[i] = rsqrtf((float)(c + 1));
    }
}

// ---------------- GEMM1: hs1h = fp16( X @ W1 )  (unscaled; edge-independent) ----------------
#define SWZ1(r, k) ((k) ^ ((((r) >> 3) & 3) << 3))
__global__ void __launch_bounds__(128) k_gemm1(const float* __restrict__ x,
                                               const float* __restrict__ W) {
    __shared__ float Xs[128][64];            // 32 KB (swizzled k)
    __shared__ float Ws[64][64];             // 16 KB
    int t = threadIdx.x;
    int row0 = blockIdx.x * 128;

    for (int i = t; i < 64 * 16; i += 128) {
        int k = i >> 4, c = (i & 15) * 4;
        *(float4*)&Ws[k][c] = *(const float4*)(W + k * 64 + c);
    }
    {
        int rl = t >> 4;
        int kg = (t & 15) * 4;
        #pragma unroll
        for (int i = 0; i < 16; i++) {
            int r = rl + i * 8;
            int gr = row0 + r;
            float4 v = make_float4(0.f, 0.f, 0.f, 0.f);
            if (gr < N_NODES) v = *(const float4*)(x + gr * 64 + kg);
            *(float4*)&Xs[r][SWZ1(r, kg)] = v;
        }
    }
    __syncthreads();

    int tx = t & 7, ty = t >> 3;
    int cb = tx * 8, rb = ty * 8;
    float acc[8][8];
    #pragma unroll
    for (int i = 0; i < 8; i++)
        #pragma unroll
        for (int j = 0; j < 8; j++) acc[i][j] = 0.f;

    #pragma unroll
    for (int k = 0; k < 64; k++) {
        float wv[8];
        *(float4*)&wv[0] = *(float4*)&Ws[k][cb];
        *(float4*)&wv[4] = *(float4*)&Ws[k][cb + 4];
        float xv[8];
        #pragma unroll
        for (int i = 0; i < 8; i++) xv[i] = Xs[rb + i][SWZ1(rb + i, k)];
        #pragma unroll
        for (int i = 0; i < 8; i++)
            #pragma unroll
            for (int j = 0; j < 8; j++) acc[i][j] = fmaf(xv[i], wv[j], acc[i][j]);
    }

    #pragma unroll
    for (int i = 0; i < 8; i++) {
        int r = row0 + rb + i;
        if (r < N_NODES) {
            __half2 h[4];
            #pragma unroll
            for (int j = 0; j < 4; j++)
                h[j] = __floats2half2_rn(acc[i][2*j], acc[i][2*j+1]);
            *(uint4*)(g_hs1h + r * 64 + cb) = *(uint4*)h;
        }
    }
}

// ---------------- agg1: x2 = relu( dn*(dn*hs[n] + sum dinv[s]*hs[s]) + b1 ) ----------------
// warp per node; lane owns half2 column (128B row); per-edge dinv[src] weight.
__global__ void __launch_bounds__(256) k_agg1(const float* __restrict__ b1) {
    int node = blockIdx.x * 8 + (threadIdx.x >> 5);
    if (node >= N_NODES) return;
    int lane = threadIdx.x & 31;
    const __half2* hs = (const __half2*)g_hs1h;

    int m = g_cnts[node];
    if (m > ELL_PAD) m = ELL_PAD;
    int base = node * ELL_PAD;
    float dn = g_dinv[node];
    float2 f = __half22float2(hs[node * 32 + lane]);        // self-loop
    float2 acc = make_float2(f.x * dn, f.y * dn);

    int j = 0;
    for (; j + 4 <= m; j += 4) {
        int s0 = g_ell[base + j + 0], s1 = g_ell[base + j + 1];
        int s2 = g_ell[base + j + 2], s3 = g_ell[base + j + 3];
        float d0 = g_dinv[s0], d1 = g_dinv[s1], d2 = g_dinv[s2], d3 = g_dinv[s3];
        float2 f0 = __half22float2(hs[s0 * 32 + lane]);
        float2 f1 = __half22float2(hs[s1 * 32 + lane]);
        float2 f2 = __half22float2(hs[s2 * 32 + lane]);
        float2 f3 = __half22float2(hs[s3 * 32 + lane]);
        acc.x += f0.x * d0 + f1.x * d1 + f2.x * d2 + f3.x * d3;
        acc.y += f0.y * d0 + f1.y * d1 + f2.y * d2 + f3.y * d3;
    }
    for (; j < m; j++) {
        int s0 = g_ell[base + j];
        float d0 = g_dinv[s0];
        float2 v = __half22float2(hs[s0 * 32 + lane]);
        acc.x += v.x * d0; acc.y += v.y * d0;
    }

    float2 bb = *(const float2*)(b1 + 2 * lane);
    float2 o;
    o.x = fmaxf(fmaf(acc.x, dn, bb.x), 0.f);
    o.y = fmaxf(fmaf(acc.y, dn, bb.y), 0.f);
    *(float2*)(g_x2 + node * 64 + 2 * lane) = o;
}

// ---------------- GEMM2: hs2h = fp16( x2 @ W2 )  (unscaled) ----------------
__global__ void __launch_bounds__(128) k_gemm2(const float* __restrict__ W) {
    __shared__ float Xs[128][65];
    __shared__ float Ws[64][32];
    int t = threadIdx.x;
    int row0 = blockIdx.x * 128;

    for (int i = t; i < 64 * 8; i += 128) {
        int k = i >> 3, c = (i & 7) * 4;
        *(float4*)&Ws[k][c] = *(const float4*)(W + k * 32 + c);
    }
    {
        int rl = t >> 4;
        int kg = (t & 15) * 4;
        #pragma unroll
        for (int i = 0; i < 16; i++) {
            int r = rl + i * 8;
            int gr = row0 + r;
            float4 v = make_float4(0.f, 0.f, 0.f, 0.f);
            if (gr < N_NODES) v = *(const float4*)(g_x2 + gr * 64 + kg);
            Xs[r][kg] = v.x; Xs[r][kg + 1] = v.y; Xs[r][kg + 2] = v.z; Xs[r][kg + 3] = v.w;
        }
    }
    __syncthreads();

    int tx = t & 7, ty = t >> 3;
    int cb = tx * 4, rb = ty * 8;
    float acc[8][4];
    #pragma unroll
    for (int i = 0; i < 8; i++)
        #pragma unroll
        for (int j = 0; j < 4; j++) acc[i][j] = 0.f;

    #pragma unroll
    for (int k = 0; k < 64; k++) {
        float wv[4];
        *(float4*)&wv[0] = *(float4*)&Ws[k][cb];
        float xv[8];
        #pragma unroll
        for (int i = 0; i < 8; i++) xv[i] = Xs[rb + i][k];
        #pragma unroll
        for (int i = 0; i < 8; i++)
            #pragma unroll
            for (int j = 0; j < 4; j++) acc[i][j] = fmaf(xv[i], wv[j], acc[i][j]);
    }

    #pragma unroll
    for (int i = 0; i < 8; i++) {
        int r = row0 + rb + i;
        if (r < N_NODES) {
            __half2 h[2];
            h[0] = __floats2half2_rn(acc[i][0], acc[i][1]);
            h[1] = __floats2half2_rn(acc[i][2], acc[i][3]);
            *(uint2*)(g_hs2h + r * 32 + cb) = *(uint2*)h;
        }
    }
}

// ---------------- agg2: out = dn*(dn*hs2[n] + sum dinv[s]*hs2[s]) + b2 ----------------
// warp per node; 2 sub-warps of 16 lanes alternate slots. No state mutation.
__global__ void __launch_bounds__(256) k_agg2(float* __restrict__ out,
                                              const float* __restrict__ b2) {
    int node = blockIdx.x * 8 + (threadIdx.x >> 5);
    if (node >= N_NODES) return;
    int lane = threadIdx.x & 31;
    int sub = lane >> 4;
    int c = lane & 15;
    const __half2* hs = (const __half2*)g_hs2h;

    int m = g_cnts[node];
    if (m > ELL_PAD) m = ELL_PAD;
    int base = node * ELL_PAD;
    float dn = g_dinv[node];
    float2 acc = make_float2(0.f, 0.f);
    if (sub == 0) {
        float2 f = __half22float2(hs[node * 16 + c]);       // self-loop
        acc.x = f.x * dn; acc.y = f.y * dn;
    }
    int j = sub;
    for (; j + 2 < m; j += 4) {              // reads j and j+2
        int s0 = g_ell[base + j], s1 = g_ell[base + j + 2];
        float d0 = g_dinv[s0], d1 = g_dinv[s1];
        float2 f0 = __half22float2(hs[s0 * 16 + c]);
        float2 f1 = __half22float2(hs[s1 * 16 + c]);
        acc.x += f0.x * d0 + f1.x * d1;
        acc.y += f0.y * d0 + f1.y * d1;
    }
    if (j < m) {
        int s0 = g_ell[base + j];
        float d0 = g_dinv[s0];
        float2 f = __half22float2(hs[s0 * 16 + c]);
        acc.x += f.x * d0; acc.y += f.y * d0;
    }
    acc.x += __shfl_xor_sync(0xffffffffu, acc.x, 16);
    acc.y += __shfl_xor_sync(0xffffffffu, acc.y, 16);
    if (sub == 0) {
        float2 bb = *(const float2*)(b2 + 2 * c);
        float2 o = make_float2(fmaf(acc.x, dn, bb.x), fmaf(acc.y, dn, bb.y));
        *(float2*)(out + node * 32 + 2 * c) = o;
    }
}

// ---------------- side-stream resources (CPU objects, created once) ----------------
struct SideRes {
    cudaStream_t s;
    cudaEvent_t fork, join;
    SideRes() {
        cudaStreamCreateWithFlags(&s, cudaStreamNonBlocking);
        cudaEventCreateWithFlags(&fork, cudaEventDisableTiming);
        cudaEventCreateWithFlags(&join, cudaEventDisableTiming);
    }
};
static SideRes& side() { static SideRes r; return r; }

// ----------------------------------------------------------------
extern "C" void kernel_launch(void* const* d_in, const int* in_sizes, int n_in,
                              void* d_out, int out_size) {
    const float* x  = (const float*)d_in[0];
    const int*   ei = (const int*)d_in[1];   // int32 (established in R2/R3)
    const float* W1 = (const float*)d_in[2];
    const float* b1 = (const float*)d_in[3];
    const float* W2 = (const float*)d_in[4];
    const float* b2 = (const float*)d_in[5];

    SideRes& r = side();

    // gemm1 (edge-independent) overlaps the single-pass ELL build
    cudaEventRecord(r.fork, (cudaStream_t)0);
    cudaStreamWaitEvent(r.s, r.fork, 0);
    k_gemm1<<<(N_NODES + 127) / 128, 128, 0, r.s>>>(x, W1);
    cudaEventRecord(r.join, r.s);

    k_permute_ell<<<(N_EDGES / 2 + 255) / 256, 256>>>(ei);
    k_dinv       <<<(N_NODES + 255) / 256, 256>>>();

    cudaStreamWaitEvent((cudaStream_t)0, r.join, 0);
    k_agg1 <<<(N_NODES + 7) / 8, 256>>>(b1);
    k_gemm2<<<(N_NODES + 127) / 128, 128>>>(W2);
    k_agg2 <<<(N_NODES + 7) / 8, 256>>>((float*)d_out, b2);
}

// round 13
// speedup vs baseline: 1.0356x; 1.0356x over previous
#include <cuda_runtime.h>
#include <cuda_fp16.h>
#include <stdint.h>

#define N_NODES 50000
#define N_EDGES 1000000
#define F_IN  64
#define F_HID 64
#define F_OUT 32
#define ELL_PAD 64          // P(deg > 64) ~ 1e-15 for Poisson(20); clamped anyway

// ---------------- scratch (device globals: allocation-free rule) ----------------
// g_cnt starts zero (module load). k_dinv consumes it (copy to g_cnts) and
// re-zeroes it, one thread per index -> no cross-block races, launch-invariant.
__device__ __align__(16) __half g_hs1h[N_NODES * F_HID];  // fp16 X@W1; scaled in-place by k_scale1
__device__ __align__(16) float  g_x2  [N_NODES * F_HID];  // relu(agg1 + b1)
__device__ __align__(16) __half g_hs2h[N_NODES * F_OUT];  // fp16 dinv*(x2@W2)
__device__ float g_dinv[N_NODES];       // rsqrt(deg), deg = cnt+1
__device__ int g_cnt [N_NODES];         // live counter (zeroed by k_dinv)
__device__ int g_cnts[N_NODES];         // stable per-launch copy for the aggs
__device__ int g_ell[N_NODES * ELL_PAD];  // 12.8MB ELL adjacency (src per slot)

// ---------------- single-pass ELL build: 2 edges/thread ----------------
__global__ void k_permute_ell(const int* __restrict__ ei) {
    int i = blockIdx.x * blockDim.x + threadIdx.x;   // pair index
    if (2 * i >= N_EDGES) return;
    int2 sv = ((const int2*)ei)[i];                  // src half
    int2 dv = ((const int2*)(ei + N_EDGES))[i];      // dst half
    int p0 = atomicAdd(&g_cnt[dv.x], 1);
    g_ell[dv.x * ELL_PAD + (p0 < ELL_PAD ? p0 : ELL_PAD - 1)] = sv.x;
    int p1 = atomicAdd(&g_cnt[dv.y], 1);
    g_ell[dv.y * ELL_PAD + (p1 < ELL_PAD ? p1 : ELL_PAD - 1)] = sv.y;
}

// ---------------- dinv + count snapshot + counter reset ----------------
// Thread i owns index i: read, copy, zero. No ordering hazards.
__global__ void k_dinv() {
    int i = blockIdx.x * blockDim.x + threadIdx.x;
    if (i < N_NODES) {
        int c = g_cnt[i];
        g_cnts[i] = c;
        g_cnt[i]  = 0;                   // ready for next launch
        g_dinv[i] = rsqrtf((float)(c + 1));
    }
}

// ---------------- scale1: hs1h *= dinv[node]  (in-place, 16B per thread) ----------------
__global__ void k_scale1() {
    int i = blockIdx.x * blockDim.x + threadIdx.x;   // uint4 index: 8 halves
    if (i >= N_NODES * 8) return;
    int node = i >> 3;
    float s = g_dinv[node];
    uint4* p = (uint4*)g_hs1h + i;
    uint4 v = *p;
    __half2* h = (__half2*)&v;
    #pragma unroll
    for (int j = 0; j < 4; j++) {
        float2 f = __half22float2(h[j]);
        h[j] = __floats2half2_rn(f.x * s, f.y * s);
    }
    *p = v;
}

// ---------------- GEMM1: hs1h = fp16( X @ W1 )  (unscaled; edge-independent) ----------------
#define SWZ1(r, k) ((k) ^ ((((r) >> 3) & 3) << 3))
__global__ void __launch_bounds__(128) k_gemm1(const float* __restrict__ x,
                                               const float* __restrict__ W) {
    __shared__ float Xs[128][64];            // 32 KB (swizzled k)
    __shared__ float Ws[64][64];             // 16 KB
    int t = threadIdx.x;
    int row0 = blockIdx.x * 128;

    for (int i = t; i < 64 * 16; i += 128) {
        int k = i >> 4, c = (i & 15) * 4;
        *(float4*)&Ws[k][c] = *(const float4*)(W + k * 64 + c);
    }
    {
        int rl = t >> 4;
        int kg = (t & 15) * 4;
        #pragma unroll
        for (int i = 0; i < 16; i++) {
            int r = rl + i * 8;
            int gr = row0 + r;
            float4 v = make_float4(0.f, 0.f, 0.f, 0.f);
            if (gr < N_NODES) v = *(const float4*)(x + gr * 64 + kg);
            *(float4*)&Xs[r][SWZ1(r, kg)] = v;
        }
    }
    __syncthreads();

    int tx = t & 7, ty = t >> 3;
    int cb = tx * 8, rb = ty * 8;
    float acc[8][8];
    #pragma unroll
    for (int i = 0; i < 8; i++)
        #pragma unroll
        for (int j = 0; j < 8; j++) acc[i][j] = 0.f;

    #pragma unroll
    for (int k = 0; k < 64; k++) {
        float wv[8];
        *(float4*)&wv[0] = *(float4*)&Ws[k][cb];
        *(float4*)&wv[4] = *(float4*)&Ws[k][cb + 4];
        float xv[8];
        #pragma unroll
        for (int i = 0; i < 8; i++) xv[i] = Xs[rb + i][SWZ1(rb + i, k)];
        #pragma unroll
        for (int i = 0; i < 8; i++)
            #pragma unroll
            for (int j = 0; j < 8; j++) acc[i][j] = fmaf(xv[i], wv[j], acc[i][j]);
    }

    #pragma unroll
    for (int i = 0; i < 8; i++) {
        int r = row0 + rb + i;
        if (r < N_NODES) {
            __half2 h[4];
            #pragma unroll
            for (int j = 0; j < 4; j++)
                h[j] = __floats2half2_rn(acc[i][2*j], acc[i][2*j+1]);
            *(uint4*)(g_hs1h + r * 64 + cb) = *(uint4*)h;
        }
    }
}

// ---------------- agg1: x2 = relu( dinv*(hs1[n] + sum hs1[src]) + b1 ) ----------------
// hs1 pre-scaled. warp per node; lane owns half2 column (128B row). Unroll x4.
__global__ void __launch_bounds__(256) k_agg1(const float* __restrict__ b1) {
    int node = blockIdx.x * 8 + (threadIdx.x >> 5);
    if (node >= N_NODES) return;
    int lane = threadIdx.x & 31;
    const __half2* hs = (const __half2*)g_hs1h;

    int m = g_cnts[node];
    if (m > ELL_PAD) m = ELL_PAD;
    int base = node * ELL_PAD;
    float2 f = __half22float2(hs[node * 32 + lane]);        // self-loop
    float2 acc = make_float2(f.x, f.y);

    int j = 0;
    for (; j + 4 <= m; j += 4) {
        int s0 = g_ell[base + j + 0], s1 = g_ell[base + j + 1];
        int s2 = g_ell[base + j + 2], s3 = g_ell[base + j + 3];
        float2 f0 = __half22float2(hs[s0 * 32 + lane]);
        float2 f1 = __half22float2(hs[s1 * 32 + lane]);
        float2 f2 = __half22float2(hs[s2 * 32 + lane]);
        float2 f3 = __half22float2(hs[s3 * 32 + lane]);
        acc.x += (f0.x + f1.x) + (f2.x + f3.x);
        acc.y += (f0.y + f1.y) + (f2.y + f3.y);
    }
    for (; j < m; j++) {
        float2 v = __half22float2(hs[g_ell[base + j] * 32 + lane]);
        acc.x += v.x; acc.y += v.y;
    }

    float s = g_dinv[node];
    float2 bb = *(const float2*)(b1 + 2 * lane);
    float2 o;
    o.x = fmaxf(fmaf(acc.x, s, bb.x), 0.f);
    o.y = fmaxf(fmaf(acc.y, s, bb.y), 0.f);
    *(float2*)(g_x2 + node * 64 + 2 * lane) = o;
}

// ---------------- GEMM2: hs2h = fp16( dinv * (x2 @ W2) )  (pre-scaled epilogue) ----------------
__global__ void __launch_bounds__(128) k_gemm2(const float* __restrict__ W) {
    __shared__ float Xs[128][65];
    __shared__ float Ws[64][32];
    int t = threadIdx.x;
    int row0 = blockIdx.x * 128;

    for (int i = t; i < 64 * 8; i += 128) {
        int k = i >> 3, c = (i & 7) * 4;
        *(float4*)&Ws[k][c] = *(const float4*)(W + k * 32 + c);
    }
    {
        int rl = t >> 4;
        int kg = (t & 15) * 4;
        #pragma unroll
        for (int i = 0; i < 16; i++) {
            int r = rl + i * 8;
            int gr = row0 + r;
            float4 v = make_float4(0.f, 0.f, 0.f, 0.f);
            if (gr < N_NODES) v = *(const float4*)(g_x2 + gr * 64 + kg);
            Xs[r][kg] = v.x; Xs[r][kg + 1] = v.y; Xs[r][kg + 2] = v.z; Xs[r][kg + 3] = v.w;
        }
    }
    __syncthreads();

    int tx = t & 7, ty = t >> 3;
    int cb = tx * 4, rb = ty * 8;
    float acc[8][4];
    #pragma unroll
    for (int i = 0; i < 8; i++)
        #pragma unroll
        for (int j = 0; j < 4; j++) acc[i][j] = 0.f;

    #pragma unroll
    for (int k = 0; k < 64; k++) {
        float wv[4];
        *(float4*)&wv[0] = *(float4*)&Ws[k][cb];
        float xv[8];
        #pragma unroll
        for (int i = 0; i < 8; i++) xv[i] = Xs[rb + i][k];
        #pragma unroll
        for (int i = 0; i < 8; i++)
            #pragma unroll
            for (int j = 0; j < 4; j++) acc[i][j] = fmaf(xv[i], wv[j], acc[i][j]);
    }

    #pragma unroll
    for (int i = 0; i < 8; i++) {
        int r = row0 + rb + i;
        if (r < N_NODES) {
            float s = g_dinv[r];
            __half2 h[2];
            h[0] = __floats2half2_rn(acc[i][0] * s, acc[i][1] * s);
            h[1] = __floats2half2_rn(acc[i][2] * s, acc[i][3] * s);
            *(uint2*)(g_hs2h + r * 32 + cb) = *(uint2*)h;
        }
    }
}

// ---------------- agg2: out = dinv*(hs2[n] + sum hs2[src]) + b2 ----------------
// hs2 pre-scaled. warp per node; 2 sub-warps of 16 lanes alternate slots.
__global__ void __launch_bounds__(256) k_agg2(float* __restrict__ out,
                                              const float* __restrict__ b2) {
    int node = blockIdx.x * 8 + (threadIdx.x >> 5);
    if (node >= N_NODES) return;
    int lane = threadIdx.x & 31;
    int sub = lane >> 4;
    int c = lane & 15;
    const __half2* hs = (const __half2*)g_hs2h;

    int m = g_cnts[node];
    if (m > ELL_PAD) m = ELL_PAD;
    int base = node * ELL_PAD;
    float2 acc = make_float2(0.f, 0.f);
    if (sub == 0) {
        float2 f = __half22float2(hs[node * 16 + c]);       // self-loop
        acc.x = f.x; acc.y = f.y;
    }
    int j = sub;
    for (; j + 2 < m; j += 4) {              // reads j and j+2
        int s0 = g_ell[base + j], s1 = g_ell[base + j + 2];
        float2 f0 = __half22float2(hs[s0 * 16 + c]);
        float2 f1 = __half22float2(hs[s1 * 16 + c]);
        acc.x += f0.x + f1.x; acc.y += f0.y + f1.y;
    }
    if (j < m) {
        float2 f = __half22float2(hs[g_ell[base + j] * 16 + c]);
        acc.x += f.x; acc.y += f.y;
    }
    acc.x += __shfl_xor_sync(0xffffffffu, acc.x, 16);
    acc.y += __shfl_xor_sync(0xffffffffu, acc.y, 16);
    if (sub == 0) {
        float s = g_dinv[node];
        float2 bb = *(const float2*)(b2 + 2 * c);
        float2 o = make_float2(fmaf(acc.x, s, bb.x), fmaf(acc.y, s, bb.y));
        *(float2*)(out + node * 32 + 2 * c) = o;
    }
}

// ---------------- side-stream resources (CPU objects, created once) ----------------
struct SideRes {
    cudaStream_t s;
    cudaEvent_t fork, join;
    SideRes() {
        cudaStreamCreateWithFlags(&s, cudaStreamNonBlocking);
        cudaEventCreateWithFlags(&fork, cudaEventDisableTiming);
        cudaEventCreateWithFlags(&join, cudaEventDisableTiming);
    }
};
static SideRes& side() { static SideRes r; return r; }

// ----------------------------------------------------------------
extern "C" void kernel_launch(void* const* d_in, const int* in_sizes, int n_in,
                              void* d_out, int out_size) {
    const float* x  = (const float*)d_in[0];
    const int*   ei = (const int*)d_in[1];   // int32 (established in R2/R3)
    const float* W1 = (const float*)d_in[2];
    const float* b1 = (const float*)d_in[3];
    const float* W2 = (const float*)d_in[4];
    const float* b2 = (const float*)d_in[5];

    SideRes& r = side();

    // gemm1 (edge-independent, unscaled) overlaps the single-pass ELL build
    cudaEventRecord(r.fork, (cudaStream_t)0);
    cudaStreamWaitEvent(r.s, r.fork, 0);
    k_gemm1<<<(N_NODES + 127) / 128, 128, 0, r.s>>>(x, W1);
    cudaEventRecord(r.join, r.s);

    k_permute_ell<<<(N_EDGES / 2 + 255) / 256, 256>>>(ei);
    k_dinv       <<<(N_NODES + 255) / 256, 256>>>();

    cudaStreamWaitEvent((cudaStream_t)0, r.join, 0);
    k_scale1<<<(N_NODES * 8 + 255) / 256, 256>>>();
    k_agg1  <<<(N_NODES + 7) / 8, 256>>>(b1);
    k_gemm2 <<<(N_NODES + 127) / 128, 128>>>(W2);
    k_agg2  <<<(N_NODES + 7) / 8, 256>>>((float*)d_out, b2);
}

// round 16
// speedup vs baseline: 1.0676x; 1.0308x over previous
#include <cuda_runtime.h>
#include <cuda_fp16.h>
#include <stdint.h>

#define N_NODES 50000
#define N_EDGES 1000000
#define F_IN  64
#define F_HID 64
#define F_OUT 32
#define ELL_PAD 64          // P(deg > 64) ~ 1e-15 for Poisson(20); clamped anyway

// ---------------- scratch (device globals: allocation-free rule) ----------------
// g_cnt starts zero (module load). k_scale1_dinv consumes it (snapshot to
// g_cnts) and re-zeroes it; the 8 threads covering one node are always in the
// same block, so read -> __syncthreads -> zero is race-free.
__device__ __align__(16) __half g_hs1h[N_NODES * F_HID];  // fp16 X@W1; scaled in place
__device__ __align__(16) float  g_x2  [N_NODES * F_HID];  // relu(agg1 + b1)
__device__ __align__(16) __half g_hs2h[N_NODES * F_OUT];  // fp16 dinv*(x2@W2)
__device__ float g_dinv[N_NODES];       // rsqrt(deg), deg = cnt+1
__device__ int g_cnt [N_NODES];         // live counter (zeroed each launch)
__device__ int g_cnts[N_NODES];         // stable per-launch snapshot
__device__ int g_ell[N_NODES * ELL_PAD];  // 12.8MB ELL adjacency (src per slot)

// ---------------- single-pass ELL build: 1 edge/thread (max atomic MLP) ----------------
__global__ void k_permute_ell(const int* __restrict__ ei) {
    int e = blockIdx.x * blockDim.x + threadIdx.x;
    if (e >= N_EDGES) return;
    int s = ei[e];
    int d = ei[N_EDGES + e];
    int p = atomicAdd(&g_cnt[d], 1);
    g_ell[d * ELL_PAD + (p < ELL_PAD ? p : ELL_PAD - 1)] = s;
}

// ---------------- scale1 + dinv + snapshot + reset (fused) ----------------
// Thread i handles uint4 chunk i of hs1 (node = i>>3). All 8 threads of a node
// are in one block: read cnt, sync, leader zeroes. Leader also writes
// g_cnts/g_dinv for downstream kernels.
__global__ void __launch_bounds__(256) k_scale1_dinv() {
    int i = blockIdx.x * 256 + threadIdx.x;
    bool valid = i < N_NODES * 8;
    int node = i >> 3;
    if (valid) {
        int c = g_cnt[node];
        float s = rsqrtf((float)(c + 1));
        uint4* p = (uint4*)g_hs1h + i;
        uint4 v = *p;
        __half2* h = (__half2*)&v;
        #pragma unroll
        for (int j = 0; j < 4; j++) {
            float2 f = __half22float2(h[j]);
            h[j] = __floats2half2_rn(f.x * s, f.y * s);
        }
        *p = v;
        if ((i & 7) == 0) { g_cnts[node] = c; g_dinv[node] = s; }
    }
    __syncthreads();                     // all reads of g_cnt in this block done
    if (valid && (i & 7) == 0) g_cnt[node] = 0;   // ready for next launch
}

// ---------------- GEMM1: hs1h = fp16( X @ W1 )  (unscaled; edge-independent) ----------------
#define SWZ1(r, k) ((k) ^ ((((r) >> 3) & 3) << 3))
__global__ void __launch_bounds__(128) k_gemm1(const float* __restrict__ x,
                                               const float* __restrict__ W) {
    __shared__ float Xs[128][64];            // 32 KB (swizzled k)
    __shared__ float Ws[64][64];             // 16 KB
    int t = threadIdx.x;
    int row0 = blockIdx.x * 128;

    for (int i = t; i < 64 * 16; i += 128) {
        int k = i >> 4, c = (i & 15) * 4;
        *(float4*)&Ws[k][c] = *(const float4*)(W + k * 64 + c);
    }
    {
        int rl = t >> 4;
        int kg = (t & 15) * 4;
        #pragma unroll
        for (int i = 0; i < 16; i++) {
            int r = rl + i * 8;
            int gr = row0 + r;
            float4 v = make_float4(0.f, 0.f, 0.f, 0.f);
            if (gr < N_NODES) v = *(const float4*)(x + gr * 64 + kg);
            *(float4*)&Xs[r][SWZ1(r, kg)] = v;
        }
    }
    __syncthreads();

    int tx = t & 7, ty = t >> 3;
    int cb = tx * 8, rb = ty * 8;
    float acc[8][8];
    #pragma unroll
    for (int i = 0; i < 8; i++)
        #pragma unroll
        for (int j = 0; j < 8; j++) acc[i][j] = 0.f;

    #pragma unroll
    for (int k = 0; k < 64; k++) {
        float wv[8];
        *(float4*)&wv[0] = *(float4*)&Ws[k][cb];
        *(float4*)&wv[4] = *(float4*)&Ws[k][cb + 4];
        float xv[8];
        #pragma unroll
        for (int i = 0; i < 8; i++) xv[i] = Xs[rb + i][SWZ1(rb + i, k)];
        #pragma unroll
        for (int i = 0; i < 8; i++)
            #pragma unroll
            for (int j = 0; j < 8; j++) acc[i][j] = fmaf(xv[i], wv[j], acc[i][j]);
    }

    #pragma unroll
    for (int i = 0; i < 8; i++) {
        int r = row0 + rb + i;
        if (r < N_NODES) {
            __half2 h[4];
            #pragma unroll
            for (int j = 0; j < 4; j++)
                h[j] = __floats2half2_rn(acc[i][2*j], acc[i][2*j+1]);
            *(uint4*)(g_hs1h + r * 64 + cb) = *(uint4*)h;
        }
    }
}

// ---------------- agg1: x2 = relu( dinv*(hs1[n] + sum hs1[src]) + b1 ) ----------------
// hs1 pre-scaled. warp per node; lane owns half2 column (128B row).
// Unroll x8 with 4 independent accumulators for MLP.
__global__ void __launch_bounds__(256) k_agg1(const float* __restrict__ b1) {
    int node = blockIdx.x * 8 + (threadIdx.x >> 5);
    if (node >= N_NODES) return;
    int lane = threadIdx.x & 31;
    const __half2* hs = (const __half2*)g_hs1h;

    int m = g_cnts[node];
    if (m > ELL_PAD) m = ELL_PAD;
    int base = node * ELL_PAD;
    float2 a0 = __half22float2(hs[node * 32 + lane]);       // self-loop
    float2 a1 = make_float2(0.f, 0.f);
    float2 a2 = make_float2(0.f, 0.f);
    float2 a3 = make_float2(0.f, 0.f);

    int j = 0;
    for (; j + 8 <= m; j += 8) {
        int s0 = g_ell[base + j + 0], s1 = g_ell[base + j + 1];
        int s2 = g_ell[base + j + 2], s3 = g_ell[base + j + 3];
        int s4 = g_ell[base + j + 4], s5 = g_ell[base + j + 5];
        int s6 = g_ell[base + j + 6], s7 = g_ell[base + j + 7];
        float2 f0 = __half22float2(hs[s0 * 32 + lane]);
        float2 f1 = __half22float2(hs[s1 * 32 + lane]);
        float2 f2 = __half22float2(hs[s2 * 32 + lane]);
        float2 f3 = __half22float2(hs[s3 * 32 + lane]);
        float2 f4 = __half22float2(hs[s4 * 32 + lane]);
        float2 f5 = __half22float2(hs[s5 * 32 + lane]);
        float2 f6 = __half22float2(hs[s6 * 32 + lane]);
        float2 f7 = __half22float2(hs[s7 * 32 + lane]);
        a0.x += f0.x + f4.x; a0.y += f0.y + f4.y;
        a1.x += f1.x + f5.x; a1.y += f1.y + f5.y;
        a2.x += f2.x + f6.x; a2.y += f2.y + f6.y;
        a3.x += f3.x + f7.x; a3.y += f3.y + f7.y;
    }
    for (; j + 4 <= m; j += 4) {
        int s0 = g_ell[base + j + 0], s1 = g_ell[base + j + 1];
        int s2 = g_ell[base + j + 2], s3 = g_ell[base + j + 3];
        float2 f0 = __half22float2(hs[s0 * 32 + lane]);
        float2 f1 = __half22float2(hs[s1 * 32 + lane]);
        float2 f2 = __half22float2(hs[s2 * 32 + lane]);
        float2 f3 = __half22float2(hs[s3 * 32 + lane]);
        a0.x += f0.x; a0.y += f0.y; a1.x += f1.x; a1.y += f1.y;
        a2.x += f2.x; a2.y += f2.y; a3.x += f3.x; a3.y += f3.y;
    }
    for (; j < m; j++) {
        float2 v = __half22float2(hs[g_ell[base + j] * 32 + lane]);
        a0.x += v.x; a0.y += v.y;
    }
    float2 acc = make_float2((a0.x + a1.x) + (a2.x + a3.x),
                             (a0.y + a1.y) + (a2.y + a3.y));

    float s = g_dinv[node];
    float2 bb = *(const float2*)(b1 + 2 * lane);
    float2 o;
    o.x = fmaxf(fmaf(acc.x, s, bb.x), 0.f);
    o.y = fmaxf(fmaf(acc.y, s, bb.y), 0.f);
    *(float2*)(g_x2 + node * 64 + 2 * lane) = o;
}

// ---------------- GEMM2: hs2h = fp16( dinv * (x2 @ W2) ) ----------------
__global__ void __launch_bounds__(128) k_gemm2(const float* __restrict__ W) {
    __shared__ float Xs[128][65];
    __shared__ float Ws[64][32];
    int t = threadIdx.x;
    int row0 = blockIdx.x * 128;

    for (int i = t; i < 64 * 8; i += 128) {
        int k = i >> 3, c = (i & 7) * 4;
        *(float4*)&Ws[k][c] = *(const float4*)(W + k * 32 + c);
    }
    {
        int rl = t >> 4;
        int kg = (t & 15) * 4;
        #pragma unroll
        for (int i = 0; i < 16; i++) {
            int r = rl + i * 8;
            int gr = row0 + r;
            float4 v = make_float4(0.f, 0.f, 0.f, 0.f);
            if (gr < N_NODES) v = *(const float4*)(g_x2 + gr * 64 + kg);
            Xs[r][kg] = v.x; Xs[r][kg + 1] = v.y; Xs[r][kg + 2] = v.z; Xs[r][kg + 3] = v.w;
        }
    }
    __syncthreads();

    int tx = t & 7, ty = t >> 3;
    int cb = tx * 4, rb = ty * 8;
    float acc[8][4];
    #pragma unroll
    for (int i = 0; i < 8; i++)
        #pragma unroll
        for (int j = 0; j < 4; j++) acc[i][j] = 0.f;

    #pragma unroll
    for (int k = 0; k < 64; k++) {
        float wv[4];
        *(float4*)&wv[0] = *(float4*)&Ws[k][cb];
        float xv[8];
        #pragma unroll
        for (int i = 0; i < 8; i++) xv[i] = Xs[rb + i][k];
        #pragma unroll
        for (int i = 0; i < 8; i++)
            #pragma unroll
            for (int j = 0; j < 4; j++) acc[i][j] = fmaf(xv[i], wv[j], acc[i][j]);
    }

    #pragma unroll
    for (int i = 0; i < 8; i++) {
        int r = row0 + rb + i;
        if (r < N_NODES) {
            float s = g_dinv[r];
            __half2 h[2];
            h[0] = __floats2half2_rn(acc[i][0] * s, acc[i][1] * s);
            h[1] = __floats2half2_rn(acc[i][2] * s, acc[i][3] * s);
            *(uint2*)(g_hs2h + r * 32 + cb) = *(uint2*)h;
        }
    }
}

// ---------------- agg2: out = dinv*(hs2[n] + sum hs2[src]) + b2 ----------------
// hs2 pre-scaled. warp per node; 2 sub-warps of 16 lanes alternate slots.
__global__ void __launch_bounds__(256) k_agg2(float* __restrict__ out,
                                              const float* __restrict__ b2) {
    int node = blockIdx.x * 8 + (threadIdx.x >> 5);
    if (node >= N_NODES) return;
    int lane = threadIdx.x & 31;
    int sub = lane >> 4;
    int c = lane & 15;
    const __half2* hs = (const __half2*)g_hs2h;

    int m = g_cnts[node];
    if (m > ELL_PAD) m = ELL_PAD;
    int base = node * ELL_PAD;
    float2 acc = make_float2(0.f, 0.f);
    if (sub == 0) {
        float2 f = __half22float2(hs[node * 16 + c]);       // self-loop
        acc.x = f.x; acc.y = f.y;
    }
    int j = sub;
    for (; j + 2 < m; j += 4) {              // reads j and j+2
        int s0 = g_ell[base + j], s1 = g_ell[base + j + 2];
        float2 f0 = __half22float2(hs[s0 * 16 + c]);
        float2 f1 = __half22float2(hs[s1 * 16 + c]);
        acc.x += f0.x + f1.x; acc.y += f0.y + f1.y;
    }
    if (j < m) {
        float2 f = __half22float2(hs[g_ell[base + j] * 16 + c]);
        acc.x += f.x; acc.y += f.y;
    }
    acc.x += __shfl_xor_sync(0xffffffffu, acc.x, 16);
    acc.y += __shfl_xor_sync(0xffffffffu, acc.y, 16);
    if (sub == 0) {
        float s = g_dinv[node];
        float2 bb = *(const float2*)(b2 + 2 * c);
        float2 o = make_float2(fmaf(acc.x, s, bb.x), fmaf(acc.y, s, bb.y));
        *(float2*)(out + node * 32 + 2 * c) = o;
    }
}

// ---------------- side-stream resources (CPU objects, created once) ----------------
struct SideRes {
    cudaStream_t s;
    cudaEvent_t fork, join;
    SideRes() {
        cudaStreamCreateWithFlags(&s, cudaStreamNonBlocking);
        cudaEventCreateWithFlags(&fork, cudaEventDisableTiming);
        cudaEventCreateWithFlags(&join, cudaEventDisableTiming);
    }
};
static SideRes& side() { static SideRes r; return r; }

// ----------------------------------------------------------------
extern "C" void kernel_launch(void* const* d_in, const int* in_sizes, int n_in,
                              void* d_out, int out_size) {
    const float* x  = (const float*)d_in[0];
    const int*   ei = (const int*)d_in[1];   // int32 (established in R2/R3)
    const float* W1 = (const float*)d_in[2];
    const float* b1 = (const float*)d_in[3];
    const float* W2 = (const float*)d_in[4];
    const float* b2 = (const float*)d_in[5];

    SideRes& r = side();

    // gemm1 (edge-independent, unscaled) overlaps the single-pass ELL build
    cudaEventRecord(r.fork, (cudaStream_t)0);
    cudaStreamWaitEvent(r.s, r.fork, 0);
    k_gemm1<<<(N_NODES + 127) / 128, 128, 0, r.s>>>(x, W1);
    cudaEventRecord(r.join, r.s);

    k_permute_ell<<<(N_EDGES + 255) / 256, 256>>>(ei);

    cudaStreamWaitEvent((cudaStream_t)0, r.join, 0);
    k_scale1_dinv<<<(N_NODES * 8 + 255) / 256, 256>>>();
    k_agg1  <<<(N_NODES + 7) / 8, 256>>>(b1);
    k_gemm2 <<<(N_NODES + 127) / 128, 128>>>(W2);
    k_agg2  <<<(N_NODES + 7) / 8, 256>>>((float*)d_out, b2);
}